// round 3
// baseline (speedup 1.0000x reference)
#include <cuda_runtime.h>

// B, N, D, L = 32, 1000, 256, 3
#define BB 32
#define NN 1000
#define DD 256
#define LL 3
#define CHUNKS 25
#define ROWS_PER_CHUNK 40         // 25 * 40 = 1000
#define TOTAL4 (BB * NN * DD / 4) // 2,048,000 float4s per output half

// Scratch (no device allocation allowed -> __device__ globals)
__device__ float g_partial[BB * CHUNKS * DD];
__device__ float g_v[BB * DD];

// ---------------------------------------------------------------------------
// K1: partial sums over the node axis AND the verbatim copy half of out.
// grid (B, 25), block (64, 4): thread (x,y) = float4-col x, row-group y,
// 10 front-batched LDG.128 per thread. Copy stores use __stcs (evict-first)
// so nf stays resident in L2 for K3.
// ---------------------------------------------------------------------------
__global__ void k_partial_copy(const float* __restrict__ nf, float* __restrict__ out) {
    const int b = blockIdx.x;
    const int c = blockIdx.y;
    const int x = threadIdx.x;   // 0..63
    const int y = threadIdx.y;   // 0..3

    const float4* __restrict__ nf4 = reinterpret_cast<const float4*>(nf);
    float4* o4 = reinterpret_cast<float4*>(out);

    const int base = (b * NN + c * ROWS_PER_CHUNK) * 64;  // float4 index of chunk

    // front-batch all 10 loads
    float4 a[10];
#pragma unroll
    for (int i = 0; i < 10; i++) {
        const int r = y + 4 * i;               // rows 0..39 across 4 groups
        a[i] = nf4[base + r * 64 + x];         // 512B/warp coalesced
    }

    // stream the copy half + accumulate (two chains to break dependency)
    float4 s0 = make_float4(0.f, 0.f, 0.f, 0.f);
    float4 s1 = make_float4(0.f, 0.f, 0.f, 0.f);
#pragma unroll
    for (int i = 0; i < 10; i += 2) {
        const int r0 = y + 4 * i, r1 = y + 4 * (i + 1);
        __stcs(o4 + TOTAL4 + base + r0 * 64 + x, a[i]);
        __stcs(o4 + TOTAL4 + base + r1 * 64 + x, a[i + 1]);
        s0.x += a[i].x;     s0.y += a[i].y;     s0.z += a[i].z;     s0.w += a[i].w;
        s1.x += a[i + 1].x; s1.y += a[i + 1].y; s1.z += a[i + 1].z; s1.w += a[i + 1].w;
    }
    float4 s = make_float4(s0.x + s1.x, s0.y + s1.y, s0.z + s1.z, s0.w + s1.w);

    __shared__ float4 sm[4][64];
    sm[y][x] = s;
    __syncthreads();
    if (y == 0) {
        float4 t = sm[0][x];
        const float4 t1 = sm[1][x], t2 = sm[2][x], t3 = sm[3][x];
        t.x += t1.x + t2.x + t3.x;
        t.y += t1.y + t2.y + t3.y;
        t.z += t1.z + t2.z + t3.z;
        t.w += t1.w + t2.w + t3.w;
        reinterpret_cast<float4*>(g_partial)[(b * CHUNKS + c) * 64 + x] = t;
    }
}

// ---------------------------------------------------------------------------
// K2: finish the mean, then 3 fused 256x256 GEMVs (+bias, ReLU between).
// One CTA per batch, 1024 threads: out-column o = t&255, K-group g = t>>8.
// ---------------------------------------------------------------------------
__global__ void k_gcn_head(const float* __restrict__ Ws, const float* __restrict__ bs) {
    const int b = blockIdx.x;
    const int t = threadIdx.x;
    const int o = t & (DD - 1);
    const int g = t >> 8;       // 0..3

    __shared__ float sv[DD];
    __shared__ float part[4][DD];

    // finish mean: chunks strided over the 4 groups
    float s = 0.f;
    for (int c = g; c < CHUNKS; c += 4)
        s += g_partial[(b * CHUNKS + c) * DD + o];
    part[g][o] = s;
    __syncthreads();
    if (g == 0)
        sv[o] = (part[0][o] + part[1][o] + part[2][o] + part[3][o]) * (1.0f / (float)NN);
    __syncthreads();

#pragma unroll
    for (int l = 0; l < LL; l++) {
        const float* __restrict__ W = Ws + l * DD * DD;
        float acc = 0.f;
        const int k0 = g * 64;
#pragma unroll 8
        for (int k = k0; k < k0 + 64; k++)
            acc = fmaf(sv[k], W[k * DD + o], acc);   // coalesced, L2-resident
        part[g][o] = acc;
        __syncthreads();
        if (g == 0) {
            float r = part[0][o] + part[1][o] + part[2][o] + part[3][o] + bs[l * DD + o];
            sv[o] = (l < LL - 1) ? fmaxf(r, 0.f) : r;
        }
        __syncthreads();
    }
    if (g == 0) g_v[b * DD + o] = sv[o];
}

// ---------------------------------------------------------------------------
// K3: out[0:BND] = node_feature + v[b,:]  (nf read should be L2-hot from K1)
// 4 front-batched float4 loads per thread, streaming stores.
// ---------------------------------------------------------------------------
__global__ void k_out(const float* __restrict__ nf, float* __restrict__ out) {
    const int stride = gridDim.x * blockDim.x;           // 512,000
    const int i0 = blockIdx.x * blockDim.x + threadIdx.x;

    const float4* __restrict__ nf4 = reinterpret_cast<const float4*>(nf);
    float4* o4 = reinterpret_cast<float4*>(out);

    const int ia = i0, ib = i0 + stride, ic = i0 + 2 * stride, id = i0 + 3 * stride;

    const float4 a0 = nf4[ia];
    const float4 a1 = nf4[ib];
    const float4 a2 = nf4[ic];
    const float4 a3 = nf4[id];

#define DO_ONE(idx, a)                                                        \
    {                                                                         \
        const int i = (idx) << 2;                                             \
        const int bb = i / (NN * DD);                                         \
        const int dd = i & (DD - 1);                                          \
        const float4 v = *reinterpret_cast<const float4*>(g_v + bb * DD + dd);\
        float4 r;                                                             \
        r.x = (a).x + v.x; r.y = (a).y + v.y;                                 \
        r.z = (a).z + v.z; r.w = (a).w + v.w;                                 \
        __stcs(o4 + (idx), r);                                                \
    }

    DO_ONE(ia, a0)
    DO_ONE(ib, a1)
    DO_ONE(ic, a2)
    DO_ONE(id, a3)
#undef DO_ONE
}

extern "C" void kernel_launch(void* const* d_in, const int* in_sizes, int n_in,
                              void* d_out, int out_size) {
    // Inputs in metadata order: x (unused), node_feature, Ws, bs
    const float* nf = (const float*)d_in[1];
    const float* Ws = (const float*)d_in[2];
    const float* bs = (const float*)d_in[3];
    float* out = (float*)d_out;

    dim3 g1(BB, CHUNKS);      // 800 CTAs
    dim3 b1(64, 4);
    k_partial_copy<<<g1, b1>>>(nf, out);

    k_gcn_head<<<BB, 1024>>>(Ws, bs);

    // 2000 blocks * 256 threads * 4 float4/thread = 2,048,000 = TOTAL4 exactly
    k_out<<<2000, 256>>>(nf, out);
}

// round 4
// speedup vs baseline: 1.2209x; 1.2209x over previous
#include <cuda_runtime.h>

// B, N, D, L = 32, 1000, 256, 3
#define BB 32
#define NN 1000
#define DD 256
#define LL 3
#define CHUNKS 50
#define ROWS_PER_CHUNK 20         // 50 * 20 = 1000
#define TOTAL4 (BB * NN * DD / 4) // 2,048,000 float4s per output half

// Scratch (no device allocation allowed -> __device__ globals)
__device__ float g_partial[BB * CHUNKS * DD];
__device__ float g_v[BB * DD];

// ---------------------------------------------------------------------------
// K1: partial sums of node_feature over the node axis (pure read).
// grid (B, 50) = 1600 CTAs, block (64,4). Thread (x,y): float4-col x,
// row-group y, 5 front-batched LDG.128. Low regs -> 8 CTAs/SM.
// ---------------------------------------------------------------------------
__global__ void k_partial_mean(const float* __restrict__ nf) {
    const int b = blockIdx.x;
    const int c = blockIdx.y;
    const int x = threadIdx.x;   // 0..63
    const int y = threadIdx.y;   // 0..3

    const float4* __restrict__ nf4 = reinterpret_cast<const float4*>(nf);
    const int base = (b * NN + c * ROWS_PER_CHUNK) * 64;

    // front-batch all 5 loads (rows y, y+4, ..., y+16 of the 20-row chunk)
    float4 a0 = nf4[base + (y +  0) * 64 + x];
    float4 a1 = nf4[base + (y +  4) * 64 + x];
    float4 a2 = nf4[base + (y +  8) * 64 + x];
    float4 a3 = nf4[base + (y + 12) * 64 + x];
    float4 a4 = nf4[base + (y + 16) * 64 + x];

    float4 s;
    s.x = (a0.x + a1.x) + (a2.x + a3.x) + a4.x;
    s.y = (a0.y + a1.y) + (a2.y + a3.y) + a4.y;
    s.z = (a0.z + a1.z) + (a2.z + a3.z) + a4.z;
    s.w = (a0.w + a1.w) + (a2.w + a3.w) + a4.w;

    __shared__ float4 sm[4][64];
    sm[y][x] = s;
    __syncthreads();
    if (y == 0) {
        float4 t = sm[0][x];
        const float4 t1 = sm[1][x], t2 = sm[2][x], t3 = sm[3][x];
        t.x += t1.x + t2.x + t3.x;
        t.y += t1.y + t2.y + t3.y;
        t.z += t1.z + t2.z + t3.z;
        t.w += t1.w + t2.w + t3.w;
        reinterpret_cast<float4*>(g_partial)[(b * CHUNKS + c) * 64 + x] = t;
    }
}

// ---------------------------------------------------------------------------
// K2: finish the mean, then 3 fused 256x256 GEMVs (+bias, ReLU between).
// One CTA per batch, 1024 threads: out-column o = t&255, K-group g = t>>8.
// ---------------------------------------------------------------------------
__global__ void k_gcn_head(const float* __restrict__ Ws, const float* __restrict__ bs) {
    const int b = blockIdx.x;
    const int t = threadIdx.x;
    const int o = t & (DD - 1);
    const int g = t >> 8;       // 0..3

    __shared__ float sv[DD];
    __shared__ float part[4][DD];

    // finish mean: chunks strided over the 4 groups
    float s = 0.f;
    for (int c = g; c < CHUNKS; c += 4)
        s += g_partial[(b * CHUNKS + c) * DD + o];
    part[g][o] = s;
    __syncthreads();
    if (g == 0)
        sv[o] = (part[0][o] + part[1][o] + part[2][o] + part[3][o]) * (1.0f / (float)NN);
    __syncthreads();

#pragma unroll
    for (int l = 0; l < LL; l++) {
        const float* __restrict__ W = Ws + l * DD * DD;
        float acc = 0.f;
        const int k0 = g * 64;
#pragma unroll 8
        for (int k = k0; k < k0 + 64; k++)
            acc = fmaf(sv[k], W[k * DD + o], acc);   // coalesced, L2-resident
        part[g][o] = acc;
        __syncthreads();
        if (g == 0) {
            float r = part[0][o] + part[1][o] + part[2][o] + part[3][o] + bs[l * DD + o];
            sv[o] = (l < LL - 1) ? fmaxf(r, 0.f) : r;
        }
        __syncthreads();
    }
    if (g == 0) g_v[b * DD + o] = sv[o];
}

// ---------------------------------------------------------------------------
// K3: out[0:BND]     = node_feature + v[b,:]  (nf read L2-hot after K1)
//     out[BND:2BND]  = node_feature (copy)
// 4 front-batched float4 loads per thread, streaming stores.
// ---------------------------------------------------------------------------
__global__ void k_out(const float* __restrict__ nf, float* __restrict__ out) {
    const int stride = gridDim.x * blockDim.x;           // 512,000
    const int i0 = blockIdx.x * blockDim.x + threadIdx.x;

    const float4* __restrict__ nf4 = reinterpret_cast<const float4*>(nf);
    float4* o4 = reinterpret_cast<float4*>(out);

    const int ia = i0, ib = i0 + stride, ic = i0 + 2 * stride, id = i0 + 3 * stride;

    const float4 a0 = nf4[ia];
    const float4 a1 = nf4[ib];
    const float4 a2 = nf4[ic];
    const float4 a3 = nf4[id];

#define DO_ONE(idx, a)                                                        \
    {                                                                         \
        const int i = (idx) << 2;                                             \
        const int bb = i / (NN * DD);                                         \
        const int dd = i & (DD - 1);                                          \
        const float4 v = *reinterpret_cast<const float4*>(g_v + bb * DD + dd);\
        float4 r;                                                             \
        r.x = (a).x + v.x; r.y = (a).y + v.y;                                 \
        r.z = (a).z + v.z; r.w = (a).w + v.w;                                 \
        __stcs(o4 + (idx), r);                                                \
        __stcs(o4 + TOTAL4 + (idx), (a));                                     \
    }

    DO_ONE(ia, a0)
    DO_ONE(ib, a1)
    DO_ONE(ic, a2)
    DO_ONE(id, a3)
#undef DO_ONE
}

extern "C" void kernel_launch(void* const* d_in, const int* in_sizes, int n_in,
                              void* d_out, int out_size) {
    // Inputs in metadata order: x (unused), node_feature, Ws, bs
    const float* nf = (const float*)d_in[1];
    const float* Ws = (const float*)d_in[2];
    const float* bs = (const float*)d_in[3];
    float* out = (float*)d_out;

    dim3 g1(BB, CHUNKS);      // 1600 CTAs
    dim3 b1(64, 4);
    k_partial_mean<<<g1, b1>>>(nf);

    k_gcn_head<<<BB, 1024>>>(Ws, bs);

    // 2000 blocks * 256 threads * 4 float4/thread = 2,048,000 = TOTAL4 exactly
    k_out<<<2000, 256>>>(nf, out);
}